// round 6
// baseline (speedup 1.0000x reference)
#include <cuda_runtime.h>
#include <math.h>
#include <cstdint>

#define B_  4
#define T_  2048
#define DH  512
#define H_  8
#define ND  4096
#define BT  8192
#define TM  128
#define TN  128
#define KC  32
#define NSTAGE 3
#define SSZ (2 * TM * 32 * 4)            // stage bytes (A+B) = 32768
#define SMEM_BYTES (NSTAGE * SSZ)        // 98304

// ---------------- scratch (device globals: allocation-free) ----------------
__device__ float g_q [(size_t)BT * ND];             // tf32-rounded, k-permuted
__device__ float g_k [(size_t)BT * ND];
__device__ float g_vt[(size_t)B_ * ND * T_];        // [b][h*DH+d][t-perm]
__device__ float g_s [(size_t)B_ * H_ * T_ * T_];   // scores/probs, j-permuted
__device__ float g_wt[3 * (size_t)ND * DH];         // W^T, k-permuted
__device__ float g_qr[(size_t)BT * DH];             // query, k-permuted
__device__ float g_vr[(size_t)BT * DH];             // value, k-permuted

__device__ __forceinline__ int tr4(int x) { return ((x & 3) << 2) | (x >> 2); }
__device__ __forceinline__ uint32_t f2tf32(float x) {
    uint32_t o; asm("cvt.rna.tf32.f32 %0, %1;" : "=r"(o) : "f"(x)); return o;
}
__device__ __forceinline__ float rtf(float x) { return __uint_as_float(f2tf32(x)); }
__device__ __forceinline__ uint32_t smem_u32(const void* p) {
    uint32_t a;
    asm("{ .reg .u64 t; cvta.to.shared.u64 t, %1; cvt.u32.u64 %0, t; }" : "=r"(a) : "l"(p));
    return a;
}
__device__ __forceinline__ void cp_async16(uint32_t saddr, const float* gaddr) {
    asm volatile("cp.async.cg.shared.global [%0], [%1], 16;" :: "r"(saddr), "l"(gaddr));
}
#define CP_COMMIT() asm volatile("cp.async.commit_group;" ::: "memory")
#define CP_WAIT1()  asm volatile("cp.async.wait_group 1;" ::: "memory")
#define CP_WAIT0()  asm volatile("cp.async.wait_group 0;" ::: "memory")

#define LDS4(v, base, IMM) \
    asm volatile("ld.shared.v4.b32 {%0,%1,%2,%3}, [%4+" IMM "];" \
        : "=r"((v).x), "=r"((v).y), "=r"((v).z), "=r"((v).w) : "r"(base))

__device__ __forceinline__ void mma_tf32(float* c,
                                         uint32_t a0, uint32_t a1, uint32_t a2, uint32_t a3,
                                         uint32_t b0, uint32_t b1) {
    asm volatile("mma.sync.aligned.m16n8k8.row.col.f32.tf32.tf32.f32 "
                 "{%0,%1,%2,%3}, {%4,%5,%6,%7}, {%8,%9}, {%0,%1,%2,%3};"
                 : "+f"(c[0]), "+f"(c[1]), "+f"(c[2]), "+f"(c[3])
                 : "r"(a0), "r"(a1), "r"(a2), "r"(a3), "r"(b0), "r"(b1));
}

// ======================= generic tf32 mma.sync GEMM =======================
struct GemmArgs {
    const float* A; long long sAz, sAh; int lda;
    const float* B; long long sBz, sBh; int ldb;
    float*       C; long long sCz, sCh; int ldc;
    int K; int zHeads;
    const float* bias; int biasMode;   // 0 none, 1 by-col, 2 by-row
    float scale;
    int causal;                        // 0 none, 1 skip tj>ti, 2 kmax=m0+TM
    int roundC;
    int permC;                         // permute output cols (tr4 in 16-groups)
};

__global__ __launch_bounds__(256, 2) void gemm_tc(GemmArgs ga)
{
    const int ti = blockIdx.y, tj = blockIdx.x, z = blockIdx.z;
    if (ga.causal == 1 && tj > ti) return;

    extern __shared__ uint32_t smem[];
    const uint32_t sb = smem_u32(smem);

    const int tid  = threadIdx.x;
    const int wid  = tid >> 5, lane = tid & 31;
    const int wm   = wid >> 2, wn = wid & 3;
    const int gid  = lane >> 2, tig = lane & 3;
    const int m0 = ti * TM, n0 = tj * TN;
    const int px = (gid & 1) << 2;

    int kmax = ga.K;
    if (ga.causal == 2) kmax = min(kmax, m0 + TM);
    const int NC = kmax / KC;

    const int zb = z / ga.zHeads, zh = z - zb * ga.zHeads;
    const float* Ag = ga.A + (size_t)zb * ga.sAz + (size_t)zh * ga.sAh;
    const float* Bg = ga.B + (size_t)zb * ga.sBz + (size_t)zh * ga.sBh;

    // ---- producer setup: 4 x (row, chunk) 16B loads per matrix ----
    int soff[4];
    const float *pA[4], *pB[4];
#pragma unroll
    for (int i = 0; i < 4; ++i) {
        const int id = i * 256 + tid;
        const int row = id >> 3, ch = id & 7;
        soff[i] = (row * 8 + (ch ^ ((row & 1) << 2))) * 16;
        pA[i] = Ag + (size_t)(m0 + row) * ga.lda + ch * 4;
        pB[i] = Bg + (size_t)(n0 + row) * ga.ldb + ch * 4;
    }
    uint32_t prodBase = sb;
    int ps = 0;

#define ISSUE() do {                                                    \
        _Pragma("unroll")                                               \
        for (int _i = 0; _i < 4; ++_i) {                                \
            cp_async16(prodBase + soff[_i], pA[_i]);                    \
            cp_async16(prodBase + 16384 + soff[_i], pB[_i]);            \
            pA[_i] += KC; pB[_i] += KC;                                 \
        }                                                               \
        CP_COMMIT();                                                    \
        prodBase += (ps == NSTAGE - 1) ? (uint32_t)(0u - 2u * SSZ) : SSZ; \
        ps = (ps == NSTAGE - 1) ? 0 : ps + 1;                           \
    } while (0)

    // ---- consumer fragment base addresses (stage 0) ----
    const int pc0 = tig ^ px, pc1 = (4 + tig) ^ px;
    uint32_t aB[2], bB[2];
    aB[0] = sb + ((wm * 64 + gid) * 8 + pc0) * 16;
    aB[1] = sb + ((wm * 64 + gid) * 8 + pc1) * 16;
    bB[0] = sb + 16384 + ((wn * 32 + gid) * 8 + pc0) * 16;
    bB[1] = sb + 16384 + ((wn * 32 + gid) * 8 + pc1) * 16;
    int fs = 0;

    float acc[4][4][4];
#pragma unroll
    for (int mt = 0; mt < 4; ++mt)
#pragma unroll
        for (int nt = 0; nt < 4; ++nt)
#pragma unroll
            for (int r = 0; r < 4; ++r) acc[mt][nt][r] = 0.f;

    ISSUE();
    ISSUE();

    for (int c = 0; c < NC; ++c) {
        if (c == NC - 1) CP_WAIT0(); else CP_WAIT1();
        __syncthreads();
        if (c + 2 < NC) ISSUE();

#pragma unroll
        for (int g = 0; g < 2; ++g) {
            const uint32_t ab = aB[g], bb = bB[g];
            uint4 b0, b1, b2, b3, p0, p1, q0, q1;
            LDS4(b0, bb, "0");    LDS4(b1, bb, "1024");
            LDS4(b2, bb, "2048"); LDS4(b3, bb, "3072");
            // mt 0,1
            LDS4(p0, ab, "0");    LDS4(p1, ab, "1024");
            LDS4(q0, ab, "2048"); LDS4(q1, ab, "3072");
            mma_tf32(acc[0][0], p0.x, p1.x, p0.y, p1.y, b0.x, b0.y);
            mma_tf32(acc[0][1], p0.x, p1.x, p0.y, p1.y, b1.x, b1.y);
            mma_tf32(acc[0][2], p0.x, p1.x, p0.y, p1.y, b2.x, b2.y);
            mma_tf32(acc[0][3], p0.x, p1.x, p0.y, p1.y, b3.x, b3.y);
            mma_tf32(acc[1][0], q0.x, q1.x, q0.y, q1.y, b0.x, b0.y);
            mma_tf32(acc[1][1], q0.x, q1.x, q0.y, q1.y, b1.x, b1.y);
            mma_tf32(acc[1][2], q0.x, q1.x, q0.y, q1.y, b2.x, b2.y);
            mma_tf32(acc[1][3], q0.x, q1.x, q0.y, q1.y, b3.x, b3.y);
            mma_tf32(acc[0][0], p0.z, p1.z, p0.w, p1.w, b0.z, b0.w);
            mma_tf32(acc[0][1], p0.z, p1.z, p0.w, p1.w, b1.z, b1.w);
            mma_tf32(acc[0][2], p0.z, p1.z, p0.w, p1.w, b2.z, b2.w);
            mma_tf32(acc[0][3], p0.z, p1.z, p0.w, p1.w, b3.z, b3.w);
            mma_tf32(acc[1][0], q0.z, q1.z, q0.w, q1.w, b0.z, b0.w);
            mma_tf32(acc[1][1], q0.z, q1.z, q0.w, q1.w, b1.z, b1.w);
            mma_tf32(acc[1][2], q0.z, q1.z, q0.w, q1.w, b2.z, b2.w);
            mma_tf32(acc[1][3], q0.z, q1.z, q0.w, q1.w, b3.z, b3.w);
            // mt 2,3
            LDS4(p0, ab, "4096"); LDS4(p1, ab, "5120");
            LDS4(q0, ab, "6144"); LDS4(q1, ab, "7168");
            mma_tf32(acc[2][0], p0.x, p1.x, p0.y, p1.y, b0.x, b0.y);
            mma_tf32(acc[2][1], p0.x, p1.x, p0.y, p1.y, b1.x, b1.y);
            mma_tf32(acc[2][2], p0.x, p1.x, p0.y, p1.y, b2.x, b2.y);
            mma_tf32(acc[2][3], p0.x, p1.x, p0.y, p1.y, b3.x, b3.y);
            mma_tf32(acc[3][0], q0.x, q1.x, q0.y, q1.y, b0.x, b0.y);
            mma_tf32(acc[3][1], q0.x, q1.x, q0.y, q1.y, b1.x, b1.y);
            mma_tf32(acc[3][2], q0.x, q1.x, q0.y, q1.y, b2.x, b2.y);
            mma_tf32(acc[3][3], q0.x, q1.x, q0.y, q1.y, b3.x, b3.y);
            mma_tf32(acc[2][0], p0.z, p1.z, p0.w, p1.w, b0.z, b0.w);
            mma_tf32(acc[2][1], p0.z, p1.z, p0.w, p1.w, b1.z, b1.w);
            mma_tf32(acc[2][2], p0.z, p1.z, p0.w, p1.w, b2.z, b2.w);
            mma_tf32(acc[2][3], p0.z, p1.z, p0.w, p1.w, b3.z, b3.w);
            mma_tf32(acc[3][0], q0.z, q1.z, q0.w, q1.w, b0.z, b0.w);
            mma_tf32(acc[3][1], q0.z, q1.z, q0.w, q1.w, b1.z, b1.w);
            mma_tf32(acc[3][2], q0.z, q1.z, q0.w, q1.w, b2.z, b2.w);
            mma_tf32(acc[3][3], q0.z, q1.z, q0.w, q1.w, b3.z, b3.w);
        }
        const uint32_t fd = (fs == NSTAGE - 1) ? (uint32_t)(0u - 2u * SSZ) : SSZ;
        aB[0] += fd; aB[1] += fd; bB[0] += fd; bB[1] += fd;
        fs = (fs == NSTAGE - 1) ? 0 : fs + 1;
    }

    // ---------------- epilogue ----------------
    float* Cb = ga.C + (size_t)zb * ga.sCz + (size_t)zh * ga.sCh;
#pragma unroll
    for (int mt = 0; mt < 4; ++mt) {
        const int row0 = m0 + wm * 64 + mt * 16 + gid;
#pragma unroll
        for (int nt = 0; nt < 4; ++nt) {
            const int cl = wn * 32 + nt * 8 + tig * 2;
            float ba0 = 0.f, ba1 = 0.f, bb0 = 0.f, bb1 = 0.f;
            if (ga.biasMode == 1) {
                ba0 = bb0 = ga.bias[n0 + cl];
                ba1 = bb1 = ga.bias[n0 + cl + 1];
            } else if (ga.biasMode == 2) {
                ba0 = ba1 = ga.bias[row0];
                bb0 = bb1 = ga.bias[row0 + 8];
            }
            float v00 = acc[mt][nt][0] * ga.scale + ba0;
            float v01 = acc[mt][nt][1] * ga.scale + ba1;
            float v10 = acc[mt][nt][2] * ga.scale + bb0;
            float v11 = acc[mt][nt][3] * ga.scale + bb1;
            if (ga.roundC) { v00 = rtf(v00); v01 = rtf(v01); v10 = rtf(v10); v11 = rtf(v11); }
            float* r0 = Cb + (size_t)row0 * ga.ldc;
            float* r1 = Cb + (size_t)(row0 + 8) * ga.ldc;
            if (ga.permC) {
                const int p0 = n0 + (cl & ~15) + tr4(cl & 15);
                const int p1 = n0 + ((cl + 1) & ~15) + tr4((cl + 1) & 15);
                r0[p0] = v00; r0[p1] = v01;
                r1[p0] = v10; r1[p1] = v11;
            } else {
                *(float2*)(r0 + n0 + cl) = make_float2(v00, v01);
                *(float2*)(r1 + n0 + cl) = make_float2(v10, v11);
            }
        }
    }
#undef ISSUE
}

// ========= round + k-permute copy =========
__global__ __launch_bounds__(256) void round_perm(
    const float* __restrict__ in, float* __restrict__ out, int n4)
{
    const int i4 = blockIdx.x * 256 + threadIdx.x;
    if (i4 < n4) {
        const int s = i4 * 4;
        const int base = s & ~15, j = (s >> 2) & 3;
        float4 v;
        v.x = rtf(in[base + j]);
        v.y = rtf(in[base + 4 + j]);
        v.z = rtf(in[base + 8 + j]);
        v.w = rtf(in[base + 12 + j]);
        ((float4*)out)[i4] = v;
    }
}

// ===== W transpose + round + k-permute =====
__global__ __launch_bounds__(256) void transpose_w(
    const float* __restrict__ W0, const float* __restrict__ W1,
    const float* __restrict__ W2, float* __restrict__ Wt)
{
    __shared__ float t[32][33];
    const float* W = (blockIdx.z == 0) ? W0 : (blockIdx.z == 1) ? W1 : W2;
    float* O = Wt + (size_t)blockIdx.z * ND * DH;
    const int x0 = blockIdx.x * 32, y0 = blockIdx.y * 32;
    const int tx = threadIdx.x, ty = threadIdx.y;
#pragma unroll
    for (int i = 0; i < 32; i += 8)
        t[ty + i][tx] = W[(size_t)(y0 + ty + i) * ND + x0 + tx];
    __syncthreads();
    const int kp = y0 + (tx & 16) + tr4(tx & 15);
#pragma unroll
    for (int i = 0; i < 32; i += 8)
        O[(size_t)(x0 + ty + i) * DH + kp] = rtf(t[tx][ty + i]);
}

// ==== causal softmax on j-permuted scores: elementwise, float4 in/out ====
// storage s holds logical j = (s & ~15) | tr4(s & 15); reductions are
// permutation-invariant, masking uses the logical index.
__global__ __launch_bounds__(256) void softmax_rows(float* __restrict__ S)
{
    const int r = blockIdx.x, z = blockIdx.y;
    float4* row = (float4*)(S + ((size_t)z * T_ + r) * T_);
    const int L = r + 1;                      // causal length (logical)
    const int Q = ((r | 127) + 1) >> 2;       // float4 count (tile-padded)
    const int tid = threadIdx.x;
    const int wid = tid >> 5, lane = tid & 31;
    __shared__ float red[8];

    float4 v[2];
    int jb[2];
    float m = -1e30f;
#pragma unroll
    for (int it = 0; it < 2; ++it) {
        const int q = tid + it * 256;
        jb[it] = -1;
        if (q < Q) {
            v[it] = row[q];
            const int j0 = (q * 4 & ~15) + (q & 3);   // logical j of comp 0
            jb[it] = j0;
            if (j0      < L) m = fmaxf(m, v[it].x);
            if (j0 + 4  < L) m = fmaxf(m, v[it].y);
            if (j0 + 8  < L) m = fmaxf(m, v[it].z);
            if (j0 + 12 < L) m = fmaxf(m, v[it].w);
        }
    }
#pragma unroll
    for (int o = 16; o > 0; o >>= 1) m = fmaxf(m, __shfl_xor_sync(~0u, m, o));
    if (lane == 0) red[wid] = m;
    __syncthreads();
    m = fmaxf(fmaxf(fmaxf(red[0], red[1]), fmaxf(red[2], red[3])),
              fmaxf(fmaxf(red[4], red[5]), fmaxf(red[6], red[7])));
    __syncthreads();

    float sum = 0.f;
#pragma unroll
    for (int it = 0; it < 2; ++it) {
        if (jb[it] >= 0) {
            const int j0 = jb[it];
            v[it].x = (j0      < L) ? __expf(v[it].x - m) : 0.f;
            v[it].y = (j0 + 4  < L) ? __expf(v[it].y - m) : 0.f;
            v[it].z = (j0 + 8  < L) ? __expf(v[it].z - m) : 0.f;
            v[it].w = (j0 + 12 < L) ? __expf(v[it].w - m) : 0.f;
            sum += v[it].x + v[it].y + v[it].z + v[it].w;
        }
    }
#pragma unroll
    for (int o = 16; o > 0; o >>= 1) sum += __shfl_xor_sync(~0u, sum, o);
    if (lane == 0) red[wid] = sum;
    __syncthreads();
    const float inv = 1.0f / (red[0] + red[1] + red[2] + red[3] +
                              red[4] + red[5] + red[6] + red[7]);

#pragma unroll
    for (int it = 0; it < 2; ++it) {
        if (jb[it] >= 0) {
            const int q = tid + it * 256;
            float4 o;
            o.x = rtf(v[it].x * inv);
            o.y = rtf(v[it].y * inv);
            o.z = rtf(v[it].z * inv);
            o.w = rtf(v[it].w * inv);
            row[q] = o;
        }
    }
}

// =====================================================================
extern "C" void kernel_launch(void* const* d_in, const int* in_sizes, int n_in,
                              void* d_out, int out_size)
{
    const float* query = (const float*)d_in[0];
    const float* value = (const float*)d_in[1];
    const float* Wq    = (const float*)d_in[2];
    const float* bq    = (const float*)d_in[3];
    const float* Wk    = (const float*)d_in[4];
    const float* bk    = (const float*)d_in[5];
    const float* Wv    = (const float*)d_in[6];
    const float* bv    = (const float*)d_in[7];
    float* out = (float*)d_out;

    float *q, *k, *vt, *s, *wt, *qr, *vr;
    cudaGetSymbolAddress((void**)&q,  g_q);
    cudaGetSymbolAddress((void**)&k,  g_k);
    cudaGetSymbolAddress((void**)&vt, g_vt);
    cudaGetSymbolAddress((void**)&s,  g_s);
    cudaGetSymbolAddress((void**)&wt, g_wt);
    cudaGetSymbolAddress((void**)&qr, g_qr);
    cudaGetSymbolAddress((void**)&vr, g_vr);

    cudaFuncSetAttribute(gemm_tc, cudaFuncAttributeMaxDynamicSharedMemorySize, SMEM_BYTES);

    const int n4 = BT * DH / 4;
    round_perm<<<n4 / 256, 256>>>(query, qr, n4);
    round_perm<<<n4 / 256, 256>>>(value, vr, n4);
    transpose_w<<<dim3(ND / 32, DH / 32, 3), dim3(32, 8)>>>(Wq, Wk, Wv, wt);

    GemmArgs a;

    // 1. q = query @ Wq + bq   (rounded, col-permuted)
    a = { qr, 0, 0, DH,
          wt + 0 * (size_t)ND * DH, 0, 0, DH,
          q, 0, 0, ND,
          DH, 1, bq, 1, 1.0f, 0, 1, 1 };
    gemm_tc<<<dim3(ND / TN, BT / TM, 1), 256, SMEM_BYTES>>>(a);

    // 2. k = value @ Wk + bk   (rounded, col-permuted)
    a = { vr, 0, 0, DH,
          wt + 1 * (size_t)ND * DH, 0, 0, DH,
          k, 0, 0, ND,
          DH, 1, bk, 1, 1.0f, 0, 1, 1 };
    gemm_tc<<<dim3(ND / TN, BT / TM, 1), 256, SMEM_BYTES>>>(a);

    // 3. vt = Wv^T @ value^T + bv  (rounded, t-permuted)
    a = { wt + 2 * (size_t)ND * DH, 0, 0, DH,
          vr, (long long)T_ * DH, 0, DH,
          vt, (long long)ND * T_, 0, T_,
          DH, 1, bv, 2, 1.0f, 0, 1, 1 };
    gemm_tc<<<dim3(T_ / TN, ND / TM, B_), 256, SMEM_BYTES>>>(a);

    // 4. scores = scale * q @ k^T  (causal skip; j-permuted output)
    a = { q, (long long)T_ * ND, DH, ND,
          k, (long long)T_ * ND, DH, ND,
          s, 8LL * T_ * T_, (long long)T_ * T_, T_,
          DH, H_, nullptr, 0, 0.044194173824159216f, 1, 0, 1 };
    gemm_tc<<<dim3(T_ / TN, T_ / TM, B_ * H_), 256, SMEM_BYTES>>>(a);

    // 5. softmax (elementwise on permuted storage, float4 coalesced)
    softmax_rows<<<dim3(T_, B_ * H_), 256>>>(s);

    // 6. out = P @ V   (K bounded; plain output)
    a = { s, 8LL * T_ * T_, (long long)T_ * T_, T_,
          vt, (long long)ND * T_, (long long)DH * T_, T_,
          out, (long long)T_ * ND, DH, ND,
          T_, H_, nullptr, 0, 1.0f, 2, 0, 0 };
    gemm_tc<<<dim3(DH / TN, T_ / TM, B_ * H_), 256, SMEM_BYTES>>>(a);
}

// round 7
// speedup vs baseline: 1.6069x; 1.6069x over previous
#include <cuda_runtime.h>
#include <math.h>
#include <cstdint>

#define B_  4
#define T_  2048
#define DH  512
#define H_  8
#define ND  4096
#define BT  8192
#define TMM 256                          // block tile M
#define TNN 128                          // block tile N
#define KC  32
#define NSTAGE 3
#define ASZ (TMM * 32 * 4)               // 32768 B per stage (A)
#define BSZ (TNN * 32 * 4)               // 16384 B per stage (B)
#define SSZ (ASZ + BSZ)                  // 49152
#define SMEM_BYTES (NSTAGE * SSZ)        // 147456

// ---------------- scratch (device globals: allocation-free) ----------------
__device__ float g_q [(size_t)BT * ND];             // tf32-rounded, k-permuted
__device__ float g_k [(size_t)BT * ND];
__device__ float g_vt[(size_t)B_ * ND * T_];        // [b][h*DH+d][t-perm]
__device__ float g_s [(size_t)B_ * H_ * T_ * T_];   // scores/probs, j-permuted
__device__ float g_wt[3 * (size_t)ND * DH];         // W^T, k-permuted
__device__ float g_qr[(size_t)BT * DH];             // query, k-permuted
__device__ float g_vr[(size_t)BT * DH];             // value, k-permuted

__device__ __forceinline__ int tr4(int x) { return ((x & 3) << 2) | (x >> 2); }
__device__ __forceinline__ uint32_t f2tf32(float x) {
    uint32_t o; asm("cvt.rna.tf32.f32 %0, %1;" : "=r"(o) : "f"(x)); return o;
}
__device__ __forceinline__ float rtf(float x) { return __uint_as_float(f2tf32(x)); }
__device__ __forceinline__ uint32_t smem_u32(const void* p) {
    uint32_t a;
    asm("{ .reg .u64 t; cvta.to.shared.u64 t, %1; cvt.u32.u64 %0, t; }" : "=r"(a) : "l"(p));
    return a;
}
__device__ __forceinline__ void cp_async16(uint32_t saddr, const float* gaddr) {
    asm volatile("cp.async.cg.shared.global [%0], [%1], 16;" :: "r"(saddr), "l"(gaddr));
}
#define CP_COMMIT() asm volatile("cp.async.commit_group;" ::: "memory")
#define CP_WAIT1()  asm volatile("cp.async.wait_group 1;" ::: "memory")
#define CP_WAIT0()  asm volatile("cp.async.wait_group 0;" ::: "memory")

#define LDS4(v, base, IMM) \
    asm volatile("ld.shared.v4.b32 {%0,%1,%2,%3}, [%4+" IMM "];" \
        : "=r"((v).x), "=r"((v).y), "=r"((v).z), "=r"((v).w) : "r"(base))

__device__ __forceinline__ void mma_tf32(float* c,
                                         uint32_t a0, uint32_t a1, uint32_t a2, uint32_t a3,
                                         uint32_t b0, uint32_t b1) {
    asm volatile("mma.sync.aligned.m16n8k8.row.col.f32.tf32.tf32.f32 "
                 "{%0,%1,%2,%3}, {%4,%5,%6,%7}, {%8,%9}, {%0,%1,%2,%3};"
                 : "+f"(c[0]), "+f"(c[1]), "+f"(c[2]), "+f"(c[3])
                 : "r"(a0), "r"(a1), "r"(a2), "r"(a3), "r"(b0), "r"(b1));
}

// ======================= generic tf32 mma.sync GEMM =======================
// block tile 256x128, 8 warps (4x2), warp tile 64x64, KC=32, 3-stage cp.async
struct GemmArgs {
    const float* A; long long sAz, sAh; int lda;
    const float* B; long long sBz, sBh; int ldb;
    float*       C; long long sCz, sCh; int ldc;
    int K; int zHeads;
    const float* bias; int biasMode;   // 0 none, 1 by-col, 2 by-row
    float scale;
    int causal;                        // 0 none, 1 skip 128-col tj>2ti+1, 2 kmax=m0+TMM
    int roundC;
    int permC;                         // permute output cols (tr4 in 16-groups)
};

__global__ __launch_bounds__(256, 1) void gemm_tc(GemmArgs ga)
{
    const int ti = blockIdx.y, tj = blockIdx.x, z = blockIdx.z;
    if (ga.causal == 1 && tj > 2 * ti + 1) return;

    extern __shared__ uint32_t smem[];
    const uint32_t sb = smem_u32(smem);

    const int tid  = threadIdx.x;
    const int wid  = tid >> 5, lane = tid & 31;
    const int wm   = wid >> 1, wn = wid & 1;        // 4 x 2 warp grid
    const int gid  = lane >> 2, tig = lane & 3;
    const int m0 = ti * TMM, n0 = tj * TNN;
    const int px = (gid & 1) << 2;

    int kmax = ga.K;
    if (ga.causal == 2) kmax = min(kmax, m0 + TMM);
    const int NC = kmax / KC;

    const int zb = z / ga.zHeads, zh = z - zb * ga.zHeads;
    const float* Ag = ga.A + (size_t)zb * ga.sAz + (size_t)zh * ga.sAh;
    const float* Bg = ga.B + (size_t)zb * ga.sBz + (size_t)zh * ga.sBh;

    // ---- producer: A 8 x 16B, B 4 x 16B per thread per chunk ----
    int soffA[8], soffB[4];
    const float *pA[8], *pB[4];
#pragma unroll
    for (int i = 0; i < 8; ++i) {
        const int id = i * 256 + tid;
        const int row = id >> 3, ch = id & 7;
        soffA[i] = (row * 8 + (ch ^ ((row & 1) << 2))) * 16;
        pA[i] = Ag + (size_t)(m0 + row) * ga.lda + ch * 4;
    }
#pragma unroll
    for (int i = 0; i < 4; ++i) {
        const int id = i * 256 + tid;
        const int row = id >> 3, ch = id & 7;
        soffB[i] = (row * 8 + (ch ^ ((row & 1) << 2))) * 16;
        pB[i] = Bg + (size_t)(n0 + row) * ga.ldb + ch * 4;
    }
    uint32_t prodBase = sb;
    int ps = 0;

#define ISSUE() do {                                                    \
        _Pragma("unroll")                                               \
        for (int _i = 0; _i < 8; ++_i) {                                \
            cp_async16(prodBase + soffA[_i], pA[_i]);                   \
            pA[_i] += KC;                                               \
        }                                                               \
        _Pragma("unroll")                                               \
        for (int _i = 0; _i < 4; ++_i) {                                \
            cp_async16(prodBase + ASZ + soffB[_i], pB[_i]);             \
            pB[_i] += KC;                                               \
        }                                                               \
        CP_COMMIT();                                                    \
        prodBase += (ps == NSTAGE - 1) ? (uint32_t)(0u - 2u * SSZ) : SSZ; \
        ps = (ps == NSTAGE - 1) ? 0 : ps + 1;                           \
    } while (0)

    // ---- consumer fragment base addresses (stage 0) ----
    const int pc0 = tig ^ px, pc1 = (4 + tig) ^ px;
    uint32_t aB[2], bB[2];
    aB[0] = sb + (uint32_t)(((wm * 64 + gid) * 8 + pc0) * 16);
    aB[1] = sb + (uint32_t)(((wm * 64 + gid) * 8 + pc1) * 16);
    bB[0] = sb + ASZ + (uint32_t)(((wn * 64 + gid) * 8 + pc0) * 16);
    bB[1] = sb + ASZ + (uint32_t)(((wn * 64 + gid) * 8 + pc1) * 16);
    int fs = 0;

    float acc[4][8][4];
#pragma unroll
    for (int mt = 0; mt < 4; ++mt)
#pragma unroll
        for (int nt = 0; nt < 8; ++nt)
#pragma unroll
            for (int r = 0; r < 4; ++r) acc[mt][nt][r] = 0.f;

    ISSUE();
    ISSUE();

#define MT_BLOCK(mt, I0, I1)                                                 \
    do {                                                                     \
        uint4 p0, p1;                                                        \
        LDS4(p0, ab, I0); LDS4(p1, ab, I1);                                  \
        mma_tf32(acc[mt][0], p0.x, p1.x, p0.y, p1.y, b0.x, b0.y);            \
        mma_tf32(acc[mt][1], p0.x, p1.x, p0.y, p1.y, b1.x, b1.y);            \
        mma_tf32(acc[mt][2], p0.x, p1.x, p0.y, p1.y, b2.x, b2.y);            \
        mma_tf32(acc[mt][3], p0.x, p1.x, p0.y, p1.y, b3.x, b3.y);            \
        mma_tf32(acc[mt][4], p0.x, p1.x, p0.y, p1.y, b4.x, b4.y);            \
        mma_tf32(acc[mt][5], p0.x, p1.x, p0.y, p1.y, b5.x, b5.y);            \
        mma_tf32(acc[mt][6], p0.x, p1.x, p0.y, p1.y, b6.x, b6.y);            \
        mma_tf32(acc[mt][7], p0.x, p1.x, p0.y, p1.y, b7.x, b7.y);            \
        mma_tf32(acc[mt][0], p0.z, p1.z, p0.w, p1.w, b0.z, b0.w);            \
        mma_tf32(acc[mt][1], p0.z, p1.z, p0.w, p1.w, b1.z, b1.w);            \
        mma_tf32(acc[mt][2], p0.z, p1.z, p0.w, p1.w, b2.z, b2.w);            \
        mma_tf32(acc[mt][3], p0.z, p1.z, p0.w, p1.w, b3.z, b3.w);            \
        mma_tf32(acc[mt][4], p0.z, p1.z, p0.w, p1.w, b4.z, b4.w);            \
        mma_tf32(acc[mt][5], p0.z, p1.z, p0.w, p1.w, b5.z, b5.w);            \
        mma_tf32(acc[mt][6], p0.z, p1.z, p0.w, p1.w, b6.z, b6.w);            \
        mma_tf32(acc[mt][7], p0.z, p1.z, p0.w, p1.w, b7.z, b7.w);            \
    } while (0)

    for (int c = 0; c < NC; ++c) {
        if (c == NC - 1) CP_WAIT0(); else CP_WAIT1();
        __syncthreads();
        if (c + 2 < NC) ISSUE();

#pragma unroll
        for (int g = 0; g < 2; ++g) {
            const uint32_t ab = aB[g], bb = bB[g];
            uint4 b0, b1, b2, b3, b4, b5, b6, b7;
            LDS4(b0, bb, "0");    LDS4(b1, bb, "1024");
            LDS4(b2, bb, "2048"); LDS4(b3, bb, "3072");
            LDS4(b4, bb, "4096"); LDS4(b5, bb, "5120");
            LDS4(b6, bb, "6144"); LDS4(b7, bb, "7168");
            MT_BLOCK(0, "0",    "1024");
            MT_BLOCK(1, "2048", "3072");
            MT_BLOCK(2, "4096", "5120");
            MT_BLOCK(3, "6144", "7168");
        }
        const uint32_t fd = (fs == NSTAGE - 1) ? (uint32_t)(0u - 2u * SSZ) : SSZ;
        aB[0] += fd; aB[1] += fd; bB[0] += fd; bB[1] += fd;
        fs = (fs == NSTAGE - 1) ? 0 : fs + 1;
    }

    // ---------------- epilogue ----------------
    float* Cb = ga.C + (size_t)zb * ga.sCz + (size_t)zh * ga.sCh;
#pragma unroll
    for (int mt = 0; mt < 4; ++mt) {
        const int row0 = m0 + wm * 64 + mt * 16 + gid;
#pragma unroll
        for (int nt = 0; nt < 8; ++nt) {
            const int cl = wn * 64 + nt * 8 + tig * 2;
            float ba0 = 0.f, ba1 = 0.f, bb0 = 0.f, bb1 = 0.f;
            if (ga.biasMode == 1) {
                ba0 = bb0 = ga.bias[n0 + cl];
                ba1 = bb1 = ga.bias[n0 + cl + 1];
            } else if (ga.biasMode == 2) {
                ba0 = ba1 = ga.bias[row0];
                bb0 = bb1 = ga.bias[row0 + 8];
            }
            float v00 = acc[mt][nt][0] * ga.scale + ba0;
            float v01 = acc[mt][nt][1] * ga.scale + ba1;
            float v10 = acc[mt][nt][2] * ga.scale + bb0;
            float v11 = acc[mt][nt][3] * ga.scale + bb1;
            if (ga.roundC) { v00 = rtf(v00); v01 = rtf(v01); v10 = rtf(v10); v11 = rtf(v11); }
            float* r0 = Cb + (size_t)row0 * ga.ldc;
            float* r1 = Cb + (size_t)(row0 + 8) * ga.ldc;
            if (ga.permC) {
                const int p0i = n0 + (cl & ~15) + tr4(cl & 15);
                const int p1i = n0 + ((cl + 1) & ~15) + tr4((cl + 1) & 15);
                r0[p0i] = v00; r0[p1i] = v01;
                r1[p0i] = v10; r1[p1i] = v11;
            } else {
                *(float2*)(r0 + n0 + cl) = make_float2(v00, v01);
                *(float2*)(r1 + n0 + cl) = make_float2(v10, v11);
            }
        }
    }
#undef ISSUE
#undef MT_BLOCK
}

// ========= round + k-permute copy =========
__global__ __launch_bounds__(256) void round_perm(
    const float* __restrict__ in, float* __restrict__ out, int n4)
{
    const int i4 = blockIdx.x * 256 + threadIdx.x;
    if (i4 < n4) {
        const int s = i4 * 4;
        const int base = s & ~15, j = (s >> 2) & 3;
        float4 v;
        v.x = rtf(in[base + j]);
        v.y = rtf(in[base + 4 + j]);
        v.z = rtf(in[base + 8 + j]);
        v.w = rtf(in[base + 12 + j]);
        ((float4*)out)[i4] = v;
    }
}

// ===== W transpose + round + k-permute =====
__global__ __launch_bounds__(256) void transpose_w(
    const float* __restrict__ W0, const float* __restrict__ W1,
    const float* __restrict__ W2, float* __restrict__ Wt)
{
    __shared__ float t[32][33];
    const float* W = (blockIdx.z == 0) ? W0 : (blockIdx.z == 1) ? W1 : W2;
    float* O = Wt + (size_t)blockIdx.z * ND * DH;
    const int x0 = blockIdx.x * 32, y0 = blockIdx.y * 32;
    const int tx = threadIdx.x, ty = threadIdx.y;
#pragma unroll
    for (int i = 0; i < 32; i += 8)
        t[ty + i][tx] = W[(size_t)(y0 + ty + i) * ND + x0 + tx];
    __syncthreads();
    const int kp = y0 + (tx & 16) + tr4(tx & 15);
#pragma unroll
    for (int i = 0; i < 32; i += 8)
        O[(size_t)(x0 + ty + i) * DH + kp] = rtf(t[tx][ty + i]);
}

// ==== causal softmax on j-permuted scores: elementwise, float4, pad 256 ====
__global__ __launch_bounds__(256) void softmax_rows(float* __restrict__ S)
{
    const int r = blockIdx.x, z = blockIdx.y;
    float4* row = (float4*)(S + ((size_t)z * T_ + r) * T_);
    const int L = r + 1;
    const int Q = ((r | 255) + 1) >> 2;       // float4 count (256-pad for M tile)
    const int tid = threadIdx.x;
    const int wid = tid >> 5, lane = tid & 31;
    __shared__ float red[8];

    float4 v[2];
    int jb[2];
    float m = -1e30f;
#pragma unroll
    for (int it = 0; it < 2; ++it) {
        const int q = tid + it * 256;
        jb[it] = -1;
        if (q < Q) {
            v[it] = row[q];
            const int j0 = (q * 4 & ~15) + (q & 3);
            jb[it] = j0;
            if (j0      < L) m = fmaxf(m, v[it].x);
            if (j0 + 4  < L) m = fmaxf(m, v[it].y);
            if (j0 + 8  < L) m = fmaxf(m, v[it].z);
            if (j0 + 12 < L) m = fmaxf(m, v[it].w);
        }
    }
#pragma unroll
    for (int o = 16; o > 0; o >>= 1) m = fmaxf(m, __shfl_xor_sync(~0u, m, o));
    if (lane == 0) red[wid] = m;
    __syncthreads();
    m = fmaxf(fmaxf(fmaxf(red[0], red[1]), fmaxf(red[2], red[3])),
              fmaxf(fmaxf(red[4], red[5]), fmaxf(red[6], red[7])));
    __syncthreads();

    float sum = 0.f;
#pragma unroll
    for (int it = 0; it < 2; ++it) {
        if (jb[it] >= 0) {
            const int j0 = jb[it];
            v[it].x = (j0      < L) ? __expf(v[it].x - m) : 0.f;
            v[it].y = (j0 + 4  < L) ? __expf(v[it].y - m) : 0.f;
            v[it].z = (j0 + 8  < L) ? __expf(v[it].z - m) : 0.f;
            v[it].w = (j0 + 12 < L) ? __expf(v[it].w - m) : 0.f;
            sum += v[it].x + v[it].y + v[it].z + v[it].w;
        }
    }
#pragma unroll
    for (int o = 16; o > 0; o >>= 1) sum += __shfl_xor_sync(~0u, sum, o);
    if (lane == 0) red[wid] = sum;
    __syncthreads();
    const float inv = 1.0f / (red[0] + red[1] + red[2] + red[3] +
                              red[4] + red[5] + red[6] + red[7]);

#pragma unroll
    for (int it = 0; it < 2; ++it) {
        if (jb[it] >= 0) {
            const int q = tid + it * 256;
            float4 o;
            o.x = rtf(v[it].x * inv);
            o.y = rtf(v[it].y * inv);
            o.z = rtf(v[it].z * inv);
            o.w = rtf(v[it].w * inv);
            row[q] = o;
        }
    }
}

// =====================================================================
extern "C" void kernel_launch(void* const* d_in, const int* in_sizes, int n_in,
                              void* d_out, int out_size)
{
    const float* query = (const float*)d_in[0];
    const float* value = (const float*)d_in[1];
    const float* Wq    = (const float*)d_in[2];
    const float* bq    = (const float*)d_in[3];
    const float* Wk    = (const float*)d_in[4];
    const float* bk    = (const float*)d_in[5];
    const float* Wv    = (const float*)d_in[6];
    const float* bv    = (const float*)d_in[7];
    float* out = (float*)d_out;

    float *q, *k, *vt, *s, *wt, *qr, *vr;
    cudaGetSymbolAddress((void**)&q,  g_q);
    cudaGetSymbolAddress((void**)&k,  g_k);
    cudaGetSymbolAddress((void**)&vt, g_vt);
    cudaGetSymbolAddress((void**)&s,  g_s);
    cudaGetSymbolAddress((void**)&wt, g_wt);
    cudaGetSymbolAddress((void**)&qr, g_qr);
    cudaGetSymbolAddress((void**)&vr, g_vr);

    cudaFuncSetAttribute(gemm_tc, cudaFuncAttributeMaxDynamicSharedMemorySize, SMEM_BYTES);

    const int n4 = BT * DH / 4;
    round_perm<<<n4 / 256, 256>>>(query, qr, n4);
    round_perm<<<n4 / 256, 256>>>(value, vr, n4);
    transpose_w<<<dim3(ND / 32, DH / 32, 3), dim3(32, 8)>>>(Wq, Wk, Wv, wt);

    GemmArgs a;

    // 1. q = query @ Wq + bq   (rounded, col-permuted)
    a = { qr, 0, 0, DH,
          wt + 0 * (size_t)ND * DH, 0, 0, DH,
          q, 0, 0, ND,
          DH, 1, bq, 1, 1.0f, 0, 1, 1 };
    gemm_tc<<<dim3(ND / TNN, BT / TMM, 1), 256, SMEM_BYTES>>>(a);

    // 2. k = value @ Wk + bk   (rounded, col-permuted)
    a = { vr, 0, 0, DH,
          wt + 1 * (size_t)ND * DH, 0, 0, DH,
          k, 0, 0, ND,
          DH, 1, bk, 1, 1.0f, 0, 1, 1 };
    gemm_tc<<<dim3(ND / TNN, BT / TMM, 1), 256, SMEM_BYTES>>>(a);

    // 3. vt = Wv^T @ value^T + bv  (rounded, t-permuted)
    a = { wt + 2 * (size_t)ND * DH, 0, 0, DH,
          vr, (long long)T_ * DH, 0, DH,
          vt, (long long)ND * T_, 0, T_,
          DH, 1, bv, 2, 1.0f, 0, 1, 1 };
    gemm_tc<<<dim3(T_ / TNN, ND / TMM, B_), 256, SMEM_BYTES>>>(a);

    // 4. scores = scale * q @ k^T  (causal skip at 256x128; j-permuted out)
    a = { q, (long long)T_ * ND, DH, ND,
          k, (long long)T_ * ND, DH, ND,
          s, 8LL * T_ * T_, (long long)T_ * T_, T_,
          DH, H_, nullptr, 0, 0.044194173824159216f, 1, 0, 1 };
    gemm_tc<<<dim3(T_ / TNN, T_ / TMM, B_ * H_), 256, SMEM_BYTES>>>(a);

    // 5. softmax (elementwise on permuted storage, pad to 256)
    softmax_rows<<<dim3(T_, B_ * H_), 256>>>(s);

    // 6. out = P @ V   (K bounded at m0+256; plain output)
    a = { s, 8LL * T_ * T_, (long long)T_ * T_, T_,
          vt, (long long)ND * T_, (long long)DH * T_, T_,
          out, (long long)T_ * ND, DH, ND,
          T_, H_, nullptr, 0, 1.0f, 2, 0, 0 };
    gemm_tc<<<dim3(DH / TNN, T_ / TMM, B_ * H_), 256, SMEM_BYTES>>>(a);
}

// round 8
// speedup vs baseline: 1.6747x; 1.0422x over previous
#include <cuda_runtime.h>
#include <math.h>
#include <cstdint>

#define B_  4
#define T_  2048
#define DH  512
#define H_  8
#define ND  4096
#define BT  8192
#define TMM 256                          // block tile M
#define TNN 128                          // block tile N
#define KC  64                           // K floats per chunk
#define ASZ (TMM * KC * 4)               // 65536 B per stage (A)
#define BSZ (TNN * KC * 4)               // 32768 B per stage (B)
#define SSZ (ASZ + BSZ)                  // 98304
#define SMEM_BYTES (2 * SSZ)             // 196608 (2 stages)

// ---------------- scratch (device globals: allocation-free) ----------------
__device__ float g_q [(size_t)BT * ND];             // tf32-rounded, k-permuted
__device__ float g_k [(size_t)BT * ND];
__device__ float g_vt[(size_t)B_ * ND * T_];        // [b][h*DH+d][t-perm]
__device__ float g_s [(size_t)B_ * H_ * T_ * T_];   // scores/probs, j-permuted
__device__ float g_wt[3 * (size_t)ND * DH];         // W^T, k-permuted
__device__ float g_qr[(size_t)BT * DH];             // query, k-permuted
__device__ float g_vr[(size_t)BT * DH];             // value, k-permuted

__device__ __forceinline__ int tr4(int x) { return ((x & 3) << 2) | (x >> 2); }
__device__ __forceinline__ uint32_t f2tf32(float x) {
    uint32_t o; asm("cvt.rna.tf32.f32 %0, %1;" : "=r"(o) : "f"(x)); return o;
}
__device__ __forceinline__ float rtf(float x) { return __uint_as_float(f2tf32(x)); }
__device__ __forceinline__ uint32_t smem_u32(const void* p) {
    uint32_t a;
    asm("{ .reg .u64 t; cvta.to.shared.u64 t, %1; cvt.u32.u64 %0, t; }" : "=r"(a) : "l"(p));
    return a;
}
__device__ __forceinline__ void cp_async16(uint32_t saddr, const void* gaddr) {
    asm volatile("cp.async.cg.shared.global [%0], [%1], 16;" :: "r"(saddr), "l"(gaddr));
}
#define CP_COMMIT() asm volatile("cp.async.commit_group;" ::: "memory")
#define CP_WAIT0()  asm volatile("cp.async.wait_group 0;" ::: "memory")

#define LDS4(v, base, IMM) \
    asm volatile("ld.shared.v4.b32 {%0,%1,%2,%3}, [%4+" IMM "];" \
        : "=r"((v).x), "=r"((v).y), "=r"((v).z), "=r"((v).w) : "r"(base))

__device__ __forceinline__ void mma_tf32(float* c,
                                         uint32_t a0, uint32_t a1, uint32_t a2, uint32_t a3,
                                         uint32_t b0, uint32_t b1) {
    asm volatile("mma.sync.aligned.m16n8k8.row.col.f32.tf32.tf32.f32 "
                 "{%0,%1,%2,%3}, {%4,%5,%6,%7}, {%8,%9}, {%0,%1,%2,%3};"
                 : "+f"(c[0]), "+f"(c[1]), "+f"(c[2]), "+f"(c[3])
                 : "r"(a0), "r"(a1), "r"(a2), "r"(a3), "r"(b0), "r"(b1));
}

// ======================= generic tf32 mma.sync GEMM =======================
// 256x128 block, 8 warps (4x2), 64x64 warp tile, KC=64, 2-stage cp.async
struct GemmArgs {
    const float* A; long long sAz, sAh; int lda;
    const float* B; long long sBz, sBh; int ldb;
    float*       C; long long sCz, sCh; int ldc;
    int K; int zHeads;
    const float* bias; int biasMode;   // 0 none, 1 by-col, 2 by-row
    float scale;
    int causal;                        // 0 none, 1 skip tj>2ti+1, 2 kmax=m0+TMM
    int roundC;
    int permC;                         // permute output cols (tr4 in 16-groups)
};

__global__ __launch_bounds__(256, 1) void gemm_tc(GemmArgs ga)
{
    const int ti = blockIdx.y, tj = blockIdx.x, z = blockIdx.z;
    if (ga.causal == 1 && tj > 2 * ti + 1) return;

    extern __shared__ uint32_t smem[];
    const uint32_t sb = smem_u32(smem);

    const int tid  = threadIdx.x;
    const int wid  = tid >> 5, lane = tid & 31;
    const int wm   = wid >> 1, wn = wid & 1;        // 4 x 2 warp grid
    const int gid  = lane >> 2, tig = lane & 3;
    const int m0 = ti * TMM, n0 = tj * TNN;
    const int px = (gid & 1) << 2;

    int kmax = ga.K;
    if (ga.causal == 2) kmax = min(kmax, m0 + TMM);
    const int NC = kmax / KC;

    const int zb = z / ga.zHeads, zh = z - zb * ga.zHeads;
    const float* Ag = ga.A + (size_t)zb * ga.sAz + (size_t)zh * ga.sAh;
    const float* Bg = ga.B + (size_t)zb * ga.sBz + (size_t)zh * ga.sBh;

    // ---- producer: rows are 16 chunks of 16B (256B pitch) ----
    // A: 8 ptrs cover rows 0..127; partner slot = row+128 (same parity =>
    //    same swizzle) at smem +32768 and gmem +128*lda floats.
    // B: 4 ptrs cover rows 0..63; partner = row+64 at +16384 / +64*ldb.
    int soffA[8], soffB[4];
    const float *pA[8], *pB[4];
#pragma unroll
    for (int i = 0; i < 8; ++i) {
        const int id = i * 256 + tid;
        const int row = id >> 4, ch = id & 15;
        soffA[i] = (row * 16 + (ch ^ ((row & 1) << 2))) * 16;
        pA[i] = Ag + (size_t)(m0 + row) * ga.lda + ch * 4;
    }
#pragma unroll
    for (int i = 0; i < 4; ++i) {
        const int id = i * 256 + tid;
        const int row = id >> 4, ch = id & 15;
        soffB[i] = (row * 16 + (ch ^ ((row & 1) << 2))) * 16;
        pB[i] = Bg + (size_t)(n0 + row) * ga.ldb + ch * 4;
    }
    const size_t aRow128 = (size_t)128 * ga.lda;   // floats
    const size_t bRow64  = (size_t)64 * ga.ldb;
    uint32_t prodBase = sb;

#define ISSUE() do {                                                    \
        _Pragma("unroll")                                               \
        for (int _i = 0; _i < 8; ++_i) {                                \
            cp_async16(prodBase + soffA[_i], pA[_i]);                   \
            cp_async16(prodBase + soffA[_i] + 32768, pA[_i] + aRow128); \
            pA[_i] += KC;                                               \
        }                                                               \
        _Pragma("unroll")                                               \
        for (int _i = 0; _i < 4; ++_i) {                                \
            cp_async16(prodBase + ASZ + soffB[_i], pB[_i]);             \
            cp_async16(prodBase + ASZ + soffB[_i] + 16384, pB[_i] + bRow64); \
            pB[_i] += KC;                                               \
        }                                                               \
        CP_COMMIT();                                                    \
        prodBase ^= SSZ;                                                \
    } while (0)

    // ---- consumer fragment bases (stage 0); row pitch 256B ----
    const int pc0 = tig ^ px, pc1 = (4 + tig) ^ px;
    uint32_t aB[2], bB[2];
    aB[0] = sb + (uint32_t)(((wm * 64 + gid) * 16 + pc0) * 16);
    aB[1] = sb + (uint32_t)(((wm * 64 + gid) * 16 + pc1) * 16);
    bB[0] = sb + ASZ + (uint32_t)(((wn * 64 + gid) * 16 + pc0) * 16);
    bB[1] = sb + ASZ + (uint32_t)(((wn * 64 + gid) * 16 + pc1) * 16);

    float acc[4][8][4];
#pragma unroll
    for (int mt = 0; mt < 4; ++mt)
#pragma unroll
        for (int nt = 0; nt < 8; ++nt)
#pragma unroll
            for (int r = 0; r < 4; ++r) acc[mt][nt][r] = 0.f;

    ISSUE();

#define MT_BLOCK(mt, I0, I1)                                                 \
    do {                                                                     \
        uint4 p0, p1;                                                        \
        LDS4(p0, ab, I0); LDS4(p1, ab, I1);                                  \
        mma_tf32(acc[mt][0], p0.x, p1.x, p0.y, p1.y, b0.x, b0.y);            \
        mma_tf32(acc[mt][1], p0.x, p1.x, p0.y, p1.y, b1.x, b1.y);            \
        mma_tf32(acc[mt][2], p0.x, p1.x, p0.y, p1.y, b2.x, b2.y);            \
        mma_tf32(acc[mt][3], p0.x, p1.x, p0.y, p1.y, b3.x, b3.y);            \
        mma_tf32(acc[mt][4], p0.x, p1.x, p0.y, p1.y, b4.x, b4.y);            \
        mma_tf32(acc[mt][5], p0.x, p1.x, p0.y, p1.y, b5.x, b5.y);            \
        mma_tf32(acc[mt][6], p0.x, p1.x, p0.y, p1.y, b6.x, b6.y);            \
        mma_tf32(acc[mt][7], p0.x, p1.x, p0.y, p1.y, b7.x, b7.y);            \
        mma_tf32(acc[mt][0], p0.z, p1.z, p0.w, p1.w, b0.z, b0.w);            \
        mma_tf32(acc[mt][1], p0.z, p1.z, p0.w, p1.w, b1.z, b1.w);            \
        mma_tf32(acc[mt][2], p0.z, p1.z, p0.w, p1.w, b2.z, b2.w);            \
        mma_tf32(acc[mt][3], p0.z, p1.z, p0.w, p1.w, b3.z, b3.w);            \
        mma_tf32(acc[mt][4], p0.z, p1.z, p0.w, p1.w, b4.z, b4.w);            \
        mma_tf32(acc[mt][5], p0.z, p1.z, p0.w, p1.w, b5.z, b5.w);            \
        mma_tf32(acc[mt][6], p0.z, p1.z, p0.w, p1.w, b6.z, b6.w);            \
        mma_tf32(acc[mt][7], p0.z, p1.z, p0.w, p1.w, b7.z, b7.w);            \
    } while (0)

    for (int c = 0; c < NC; ++c) {
        CP_WAIT0();
        __syncthreads();
        if (c + 1 < NC) ISSUE();

        const uint32_t stg = (uint32_t)((c & 1) ? SSZ : 0);
#pragma unroll
        for (int g = 0; g < 4; ++g) {
            const uint32_t gofs = stg + (uint32_t)((g >> 1) << 7);  // +128B for chunks 8..15
            const uint32_t ab = aB[g & 1] + gofs;
            const uint32_t bb = bB[g & 1] + gofs;
            uint4 b0, b1, b2, b3, b4, b5, b6, b7;
            LDS4(b0, bb, "0");     LDS4(b1, bb, "2048");
            LDS4(b2, bb, "4096");  LDS4(b3, bb, "6144");
            LDS4(b4, bb, "8192");  LDS4(b5, bb, "10240");
            LDS4(b6, bb, "12288"); LDS4(b7, bb, "14336");
            MT_BLOCK(0, "0",     "2048");
            MT_BLOCK(1, "4096",  "6144");
            MT_BLOCK(2, "8192",  "10240");
            MT_BLOCK(3, "12288", "14336");
        }
    }

    // ---------------- epilogue ----------------
    float* Cb = ga.C + (size_t)zb * ga.sCz + (size_t)zh * ga.sCh;
#pragma unroll
    for (int mt = 0; mt < 4; ++mt) {
        const int row0 = m0 + wm * 64 + mt * 16 + gid;
#pragma unroll
        for (int nt = 0; nt < 8; ++nt) {
            const int cl = wn * 64 + nt * 8 + tig * 2;
            float ba0 = 0.f, ba1 = 0.f, bb0 = 0.f, bb1 = 0.f;
            if (ga.biasMode == 1) {
                ba0 = bb0 = ga.bias[n0 + cl];
                ba1 = bb1 = ga.bias[n0 + cl + 1];
            } else if (ga.biasMode == 2) {
                ba0 = ba1 = ga.bias[row0];
                bb0 = bb1 = ga.bias[row0 + 8];
            }
            float v00 = acc[mt][nt][0] * ga.scale + ba0;
            float v01 = acc[mt][nt][1] * ga.scale + ba1;
            float v10 = acc[mt][nt][2] * ga.scale + bb0;
            float v11 = acc[mt][nt][3] * ga.scale + bb1;
            if (ga.roundC) { v00 = rtf(v00); v01 = rtf(v01); v10 = rtf(v10); v11 = rtf(v11); }
            float* r0 = Cb + (size_t)row0 * ga.ldc;
            float* r1 = Cb + (size_t)(row0 + 8) * ga.ldc;
            if (ga.permC) {
                const int p0i = n0 + (cl & ~15) + tr4(cl & 15);
                const int p1i = n0 + ((cl + 1) & ~15) + tr4((cl + 1) & 15);
                r0[p0i] = v00; r0[p1i] = v01;
                r1[p0i] = v10; r1[p1i] = v11;
            } else {
                *(float2*)(r0 + n0 + cl) = make_float2(v00, v01);
                *(float2*)(r1 + n0 + cl) = make_float2(v10, v11);
            }
        }
    }
#undef ISSUE
#undef MT_BLOCK
}

// ========= round + k-permute copy =========
__global__ __launch_bounds__(256) void round_perm(
    const float* __restrict__ in, float* __restrict__ out, int n4)
{
    const int i4 = blockIdx.x * 256 + threadIdx.x;
    if (i4 < n4) {
        const int s = i4 * 4;
        const int base = s & ~15, j = (s >> 2) & 3;
        float4 v;
        v.x = rtf(in[base + j]);
        v.y = rtf(in[base + 4 + j]);
        v.z = rtf(in[base + 8 + j]);
        v.w = rtf(in[base + 12 + j]);
        ((float4*)out)[i4] = v;
    }
}

// ===== W transpose + round + k-permute =====
__global__ __launch_bounds__(256) void transpose_w(
    const float* __restrict__ W0, const float* __restrict__ W1,
    const float* __restrict__ W2, float* __restrict__ Wt)
{
    __shared__ float t[32][33];
    const float* W = (blockIdx.z == 0) ? W0 : (blockIdx.z == 1) ? W1 : W2;
    float* O = Wt + (size_t)blockIdx.z * ND * DH;
    const int x0 = blockIdx.x * 32, y0 = blockIdx.y * 32;
    const int tx = threadIdx.x, ty = threadIdx.y;
#pragma unroll
    for (int i = 0; i < 32; i += 8)
        t[ty + i][tx] = W[(size_t)(y0 + ty + i) * ND + x0 + tx];
    __syncthreads();
    const int kp = y0 + (tx & 16) + tr4(tx & 15);
#pragma unroll
    for (int i = 0; i < 32; i += 8)
        O[(size_t)(x0 + ty + i) * DH + kp] = rtf(t[tx][ty + i]);
}

// ==== causal softmax on j-permuted scores: elementwise, float4, pad 256 ====
__global__ __launch_bounds__(256) void softmax_rows(float* __restrict__ S)
{
    const int r = blockIdx.x, z = blockIdx.y;
    float4* row = (float4*)(S + ((size_t)z * T_ + r) * T_);
    const int L = r + 1;
    const int Q = ((r | 255) + 1) >> 2;
    const int tid = threadIdx.x;
    const int wid = tid >> 5, lane = tid & 31;
    __shared__ float red[8];

    float4 v[2];
    int jb[2];
    float m = -1e30f;
#pragma unroll
    for (int it = 0; it < 2; ++it) {
        const int q = tid + it * 256;
        jb[it] = -1;
        if (q < Q) {
            v[it] = row[q];
            const int j0 = (q * 4 & ~15) + (q & 3);
            jb[it] = j0;
            if (j0      < L) m = fmaxf(m, v[it].x);
            if (j0 + 4  < L) m = fmaxf(m, v[it].y);
            if (j0 + 8  < L) m = fmaxf(m, v[it].z);
            if (j0 + 12 < L) m = fmaxf(m, v[it].w);
        }
    }
#pragma unroll
    for (int o = 16; o > 0; o >>= 1) m = fmaxf(m, __shfl_xor_sync(~0u, m, o));
    if (lane == 0) red[wid] = m;
    __syncthreads();
    m = fmaxf(fmaxf(fmaxf(red[0], red[1]), fmaxf(red[2], red[3])),
              fmaxf(fmaxf(red[4], red[5]), fmaxf(red[6], red[7])));
    __syncthreads();

    float sum = 0.f;
#pragma unroll
    for (int it = 0; it < 2; ++it) {
        if (jb[it] >= 0) {
            const int j0 = jb[it];
            v[it].x = (j0      < L) ? __expf(v[it].x - m) : 0.f;
            v[it].y = (j0 + 4  < L) ? __expf(v[it].y - m) : 0.f;
            v[it].z = (j0 + 8  < L) ? __expf(v[it].z - m) : 0.f;
            v[it].w = (j0 + 12 < L) ? __expf(v[it].w - m) : 0.f;
            sum += v[it].x + v[it].y + v[it].z + v[it].w;
        }
    }
#pragma unroll
    for (int o = 16; o > 0; o >>= 1) sum += __shfl_xor_sync(~0u, sum, o);
    if (lane == 0) red[wid] = sum;
    __syncthreads();
    const float inv = 1.0f / (red[0] + red[1] + red[2] + red[3] +
                              red[4] + red[5] + red[6] + red[7]);

#pragma unroll
    for (int it = 0; it < 2; ++it) {
        if (jb[it] >= 0) {
            const int q = tid + it * 256;
            float4 o;
            o.x = rtf(v[it].x * inv);
            o.y = rtf(v[it].y * inv);
            o.z = rtf(v[it].z * inv);
            o.w = rtf(v[it].w * inv);
            row[q] = o;
        }
    }
}

// =====================================================================
extern "C" void kernel_launch(void* const* d_in, const int* in_sizes, int n_in,
                              void* d_out, int out_size)
{
    const float* query = (const float*)d_in[0];
    const float* value = (const float*)d_in[1];
    const float* Wq    = (const float*)d_in[2];
    const float* bq    = (const float*)d_in[3];
    const float* Wk    = (const float*)d_in[4];
    const float* bk    = (const float*)d_in[5];
    const float* Wv    = (const float*)d_in[6];
    const float* bv    = (const float*)d_in[7];
    float* out = (float*)d_out;

    float *q, *k, *vt, *s, *wt, *qr, *vr;
    cudaGetSymbolAddress((void**)&q,  g_q);
    cudaGetSymbolAddress((void**)&k,  g_k);
    cudaGetSymbolAddress((void**)&vt, g_vt);
    cudaGetSymbolAddress((void**)&s,  g_s);
    cudaGetSymbolAddress((void**)&wt, g_wt);
    cudaGetSymbolAddress((void**)&qr, g_qr);
    cudaGetSymbolAddress((void**)&vr, g_vr);

    cudaFuncSetAttribute(gemm_tc, cudaFuncAttributeMaxDynamicSharedMemorySize, SMEM_BYTES);

    const int n4 = BT * DH / 4;
    round_perm<<<n4 / 256, 256>>>(query, qr, n4);
    round_perm<<<n4 / 256, 256>>>(value, vr, n4);
    transpose_w<<<dim3(ND / 32, DH / 32, 3), dim3(32, 8)>>>(Wq, Wk, Wv, wt);

    GemmArgs a;

    // 1. q = query @ Wq + bq   (rounded, col-permuted)
    a = { qr, 0, 0, DH,
          wt + 0 * (size_t)ND * DH, 0, 0, DH,
          q, 0, 0, ND,
          DH, 1, bq, 1, 1.0f, 0, 1, 1 };
    gemm_tc<<<dim3(ND / TNN, BT / TMM, 1), 256, SMEM_BYTES>>>(a);

    // 2. k = value @ Wk + bk   (rounded, col-permuted)
    a = { vr, 0, 0, DH,
          wt + 1 * (size_t)ND * DH, 0, 0, DH,
          k, 0, 0, ND,
          DH, 1, bk, 1, 1.0f, 0, 1, 1 };
    gemm_tc<<<dim3(ND / TNN, BT / TMM, 1), 256, SMEM_BYTES>>>(a);

    // 3. vt = Wv^T @ value^T + bv  (rounded, t-permuted)
    a = { wt + 2 * (size_t)ND * DH, 0, 0, DH,
          vr, (long long)T_ * DH, 0, DH,
          vt, (long long)ND * T_, 0, T_,
          DH, 1, bv, 2, 1.0f, 0, 1, 1 };
    gemm_tc<<<dim3(T_ / TNN, ND / TMM, B_), 256, SMEM_BYTES>>>(a);

    // 4. scores = scale * q @ k^T  (causal skip; j-permuted out)
    a = { q, (long long)T_ * ND, DH, ND,
          k, (long long)T_ * ND, DH, ND,
          s, 8LL * T_ * T_, (long long)T_ * T_, T_,
          DH, H_, nullptr, 0, 0.044194173824159216f, 1, 0, 1 };
    gemm_tc<<<dim3(T_ / TNN, T_ / TMM, B_ * H_), 256, SMEM_BYTES>>>(a);

    // 5. softmax (elementwise on permuted storage, pad to 256)
    softmax_rows<<<dim3(T_, B_ * H_), 256>>>(s);

    // 6. out = P @ V   (K bounded at m0+256; plain output)
    a = { s, 8LL * T_ * T_, (long long)T_ * T_, T_,
          vt, (long long)ND * T_, (long long)DH * T_, T_,
          out, (long long)T_ * ND, DH, ND,
          T_, H_, nullptr, 0, 1.0f, 2, 0, 0 };
    gemm_tc<<<dim3(DH / TNN, T_ / TMM, B_ * H_), 256, SMEM_BYTES>>>(a);
}

// round 10
// speedup vs baseline: 2.8706x; 1.7141x over previous
#include <cuda_runtime.h>
#include <cuda_fp16.h>
#include <math.h>
#include <cstdint>

#define B_  4
#define T_  2048
#define DH  512
#define H_  8
#define ND  4096
#define BT  8192
#define TM  128
#define TN  128
#define KC  64                           // fp16 elems per chunk = 128B rows
#define NSTAGE 3
#define SSZ (2 * TM * 128)               // stage bytes (A 16KB + B 16KB) = 32768
#define SMEM_BYTES (NSTAGE * SSZ)        // 98304

// ---------------- scratch (device globals: allocation-free) ----------------
__device__ __half g_q [(size_t)BT * ND];            // fp16, pair-permuted d
__device__ __half g_k [(size_t)BT * ND];
__device__ __half g_vt[(size_t)B_ * ND * T_];       // [b][h*DH+d][t-perm] fp16
__device__ float  g_s [(size_t)B_ * H_ * T_ * T_];  // scores fp32 (plain)
__device__ __half g_p [(size_t)B_ * H_ * T_ * T_];  // probs fp16 (j-permuted)
__device__ __half g_wt[3 * (size_t)ND * DH];        // W^T fp16, k-permuted
__device__ __half g_qr[(size_t)BT * DH];            // query fp16, k-permuted
__device__ __half g_vr[(size_t)BT * DH];            // value fp16, k-permuted

__device__ __forceinline__ int tr4(int x) { return ((x & 3) << 2) | (x >> 2); }
__device__ __forceinline__ uint32_t h2u(__half2 h) {
    return *reinterpret_cast<uint32_t*>(&h);
}
__device__ __forceinline__ uint32_t smem_u32(const void* p) {
    uint32_t a;
    asm("{ .reg .u64 t; cvta.to.shared.u64 t, %1; cvt.u32.u64 %0, t; }" : "=r"(a) : "l"(p));
    return a;
}
__device__ __forceinline__ void cp_async16(uint32_t saddr, const void* gaddr) {
    asm volatile("cp.async.cg.shared.global [%0], [%1], 16;" :: "r"(saddr), "l"(gaddr));
}
#define CP_COMMIT() asm volatile("cp.async.commit_group;" ::: "memory")
#define CP_WAIT1()  asm volatile("cp.async.wait_group 1;" ::: "memory")
#define CP_WAIT0()  asm volatile("cp.async.wait_group 0;" ::: "memory")

#define LDS4(v, base, IMM) \
    asm volatile("ld.shared.v4.b32 {%0,%1,%2,%3}, [%4+" IMM "];" \
        : "=r"((v).x), "=r"((v).y), "=r"((v).z), "=r"((v).w) : "r"(base))

__device__ __forceinline__ void mma_f16(float* c,
                                        uint32_t a0, uint32_t a1, uint32_t a2, uint32_t a3,
                                        uint32_t b0, uint32_t b1) {
    asm volatile("mma.sync.aligned.m16n8k16.row.col.f32.f16.f16.f32 "
                 "{%0,%1,%2,%3}, {%4,%5,%6,%7}, {%8,%9}, {%0,%1,%2,%3};"
                 : "+f"(c[0]), "+f"(c[1]), "+f"(c[2]), "+f"(c[3])
                 : "r"(a0), "r"(a1), "r"(a2), "r"(a3), "r"(b0), "r"(b1));
}

// ======================= generic fp16 mma.sync GEMM =======================
// C[m][n] = scale * sum_k A[m][k]*B[n][k] (+bias); A,B fp16 K-major,
// pair-tr4-permuted within 32-elem k-groups. 128x128 tile, 2x4 warps,
// 64x32 warp tile, KC=64 (4 x k16 steps), 3-stage cp.async.
struct GemmArgs {
    const __half* A; long long sAz, sAh; int lda;
    const __half* B; long long sBz, sBh; int ldb;
    void*         C; long long sCz, sCh; int ldc;
    int K; int zHeads;
    const float* bias; int biasMode;   // 0 none, 1 by-col, 2 by-row
    float scale;
    int causal;                        // 0 none, 1 skip tj>ti, 2 kmax=m0+TM
    int outHalf;                       // 1: fp16 pair-permuted out, 0: fp32 plain
};

__global__ __launch_bounds__(256, 2) void gemm_tc(GemmArgs ga)
{
    const int ti = blockIdx.y, tj = blockIdx.x, z = blockIdx.z;
    if (ga.causal == 1 && tj > ti) return;

    extern __shared__ uint32_t smem[];
    const uint32_t sb = smem_u32(smem);

    const int tid  = threadIdx.x;
    const int wid  = tid >> 5, lane = tid & 31;
    const int wm   = wid >> 2, wn = wid & 3;        // 2 x 4 warp grid
    const int gid  = lane >> 2, tig = lane & 3;
    const int m0 = ti * TM, n0 = tj * TN;
    const int px = (gid & 1) << 2;

    int kmax = ga.K;
    if (ga.causal == 2) kmax = min(kmax, m0 + TM);
    const int NC = kmax / KC;

    const int zb = z / ga.zHeads, zh = z - zb * ga.zHeads;
    const __half* Ag = ga.A + (size_t)zb * ga.sAz + (size_t)zh * ga.sAh;
    const __half* Bg = ga.B + (size_t)zb * ga.sBz + (size_t)zh * ga.sBh;

    // ---- producer: rows are 8 chunks of 16B (128B pitch) ----
    int soff[4];
    const __half *pA[4], *pB[4];
#pragma unroll
    for (int i = 0; i < 4; ++i) {
        const int id = i * 256 + tid;
        const int row = id >> 3, ch = id & 7;
        soff[i] = (row * 8 + (ch ^ ((row & 1) << 2))) * 16;
        pA[i] = Ag + (size_t)(m0 + row) * ga.lda + ch * 8;
        pB[i] = Bg + (size_t)(n0 + row) * ga.ldb + ch * 8;
    }
    uint32_t prodBase = sb;
    int ps = 0;

#define ISSUE() do {                                                    \
        _Pragma("unroll")                                               \
        for (int _i = 0; _i < 4; ++_i) {                                \
            cp_async16(prodBase + soff[_i], pA[_i]);                    \
            cp_async16(prodBase + 16384 + soff[_i], pB[_i]);            \
            pA[_i] += KC; pB[_i] += KC;                                 \
        }                                                               \
        CP_COMMIT();                                                    \
        prodBase += (ps == NSTAGE - 1) ? (uint32_t)(0u - 2u * SSZ) : SSZ; \
        ps = (ps == NSTAGE - 1) ? 0 : ps + 1;                           \
    } while (0)

    // ---- consumer fragment bases (stage 0) ----
    const int pc0 = tig ^ px, pc1 = (4 + tig) ^ px;
    uint32_t aB[2], bB[2];
    aB[0] = sb + (uint32_t)(((wm * 64 + gid) * 8 + pc0) * 16);
    aB[1] = sb + (uint32_t)(((wm * 64 + gid) * 8 + pc1) * 16);
    bB[0] = sb + 16384u + (uint32_t)(((wn * 32 + gid) * 8 + pc0) * 16);
    bB[1] = sb + 16384u + (uint32_t)(((wn * 32 + gid) * 8 + pc1) * 16);
    int fs = 0;

    float acc[4][4][4];
#pragma unroll
    for (int mt = 0; mt < 4; ++mt)
#pragma unroll
        for (int nt = 0; nt < 4; ++nt)
#pragma unroll
            for (int r = 0; r < 4; ++r) acc[mt][nt][r] = 0.f;

    ISSUE();
    ISSUE();

    for (int c = 0; c < NC; ++c) {
        if (c == NC - 1) CP_WAIT0(); else CP_WAIT1();
        __syncthreads();
        if (c + 2 < NC) ISSUE();

        // g=0: k 0..31 (2 k16 steps), g=1: k 32..63
#pragma unroll
        for (int g = 0; g < 2; ++g) {
            const uint32_t ab = aB[g], bb = bB[g];
            uint4 b0, b1, b2, b3, p0, p1, q0, q1;
            LDS4(b0, bb, "0");    LDS4(b1, bb, "1024");
            LDS4(b2, bb, "2048"); LDS4(b3, bb, "3072");
            // mt 0,1
            LDS4(p0, ab, "0");    LDS4(p1, ab, "1024");
            LDS4(q0, ab, "2048"); LDS4(q1, ab, "3072");
            mma_f16(acc[0][0], p0.x, p1.x, p0.y, p1.y, b0.x, b0.y);
            mma_f16(acc[0][1], p0.x, p1.x, p0.y, p1.y, b1.x, b1.y);
            mma_f16(acc[0][2], p0.x, p1.x, p0.y, p1.y, b2.x, b2.y);
            mma_f16(acc[0][3], p0.x, p1.x, p0.y, p1.y, b3.x, b3.y);
            mma_f16(acc[1][0], q0.x, q1.x, q0.y, q1.y, b0.x, b0.y);
            mma_f16(acc[1][1], q0.x, q1.x, q0.y, q1.y, b1.x, b1.y);
            mma_f16(acc[1][2], q0.x, q1.x, q0.y, q1.y, b2.x, b2.y);
            mma_f16(acc[1][3], q0.x, q1.x, q0.y, q1.y, b3.x, b3.y);
            mma_f16(acc[0][0], p0.z, p1.z, p0.w, p1.w, b0.z, b0.w);
            mma_f16(acc[0][1], p0.z, p1.z, p0.w, p1.w, b1.z, b1.w);
            mma_f16(acc[0][2], p0.z, p1.z, p0.w, p1.w, b2.z, b2.w);
            mma_f16(acc[0][3], p0.z, p1.z, p0.w, p1.w, b3.z, b3.w);
            mma_f16(acc[1][0], q0.z, q1.z, q0.w, q1.w, b0.z, b0.w);
            mma_f16(acc[1][1], q0.z, q1.z, q0.w, q1.w, b1.z, b1.w);
            mma_f16(acc[1][2], q0.z, q1.z, q0.w, q1.w, b2.z, b2.w);
            mma_f16(acc[1][3], q0.z, q1.z, q0.w, q1.w, b3.z, b3.w);
            // mt 2,3
            LDS4(p0, ab, "4096"); LDS4(p1, ab, "5120");
            LDS4(q0, ab, "6144"); LDS4(q1, ab, "7168");
            mma_f16(acc[2][0], p0.x, p1.x, p0.y, p1.y, b0.x, b0.y);
            mma_f16(acc[2][1], p0.x, p1.x, p0.y, p1.y, b1.x, b1.y);
            mma_f16(acc[2][2], p0.x, p1.x, p0.y, p1.y, b2.x, b2.y);
            mma_f16(acc[2][3], p0.x, p1.x, p0.y, p1.y, b3.x, b3.y);
            mma_f16(acc[3][0], q0.x, q1.x, q0.y, q1.y, b0.x, b0.y);
            mma_f16(acc[3][1], q0.x, q1.x, q0.y, q1.y, b1.x, b1.y);
            mma_f16(acc[3][2], q0.x, q1.x, q0.y, q1.y, b2.x, b2.y);
            mma_f16(acc[3][3], q0.x, q1.x, q0.y, q1.y, b3.x, b3.y);
            mma_f16(acc[2][0], p0.z, p1.z, p0.w, p1.w, b0.z, b0.w);
            mma_f16(acc[2][1], p0.z, p1.z, p0.w, p1.w, b1.z, b1.w);
            mma_f16(acc[2][2], p0.z, p1.z, p0.w, p1.w, b2.z, b2.w);
            mma_f16(acc[2][3], p0.z, p1.z, p0.w, p1.w, b3.z, b3.w);
            mma_f16(acc[3][0], q0.z, q1.z, q0.w, q1.w, b0.z, b0.w);
            mma_f16(acc[3][1], q0.z, q1.z, q0.w, q1.w, b1.z, b1.w);
            mma_f16(acc[3][2], q0.z, q1.z, q0.w, q1.w, b2.z, b2.w);
            mma_f16(acc[3][3], q0.z, q1.z, q0.w, q1.w, b3.z, b3.w);
        }
        const uint32_t fd = (fs == NSTAGE - 1) ? (uint32_t)(0u - 2u * SSZ) : SSZ;
        aB[0] += fd; aB[1] += fd; bB[0] += fd; bB[1] += fd;
        fs = (fs == NSTAGE - 1) ? 0 : fs + 1;
    }

    // ---------------- epilogue ----------------
#pragma unroll
    for (int mt = 0; mt < 4; ++mt) {
        const int row0 = m0 + wm * 64 + mt * 16 + gid;
#pragma unroll
        for (int nt = 0; nt < 4; ++nt) {
            const int cl = wn * 32 + nt * 8 + tig * 2;   // even
            float ba0 = 0.f, ba1 = 0.f, bb0 = 0.f, bb1 = 0.f;
            if (ga.biasMode == 1) {
                ba0 = bb0 = ga.bias[n0 + cl];
                ba1 = bb1 = ga.bias[n0 + cl + 1];
            } else if (ga.biasMode == 2) {
                ba0 = ba1 = ga.bias[row0];
                bb0 = bb1 = ga.bias[row0 + 8];
            }
            float v00 = acc[mt][nt][0] * ga.scale + ba0;
            float v01 = acc[mt][nt][1] * ga.scale + ba1;
            float v10 = acc[mt][nt][2] * ga.scale + bb0;
            float v11 = acc[mt][nt][3] * ga.scale + bb1;
            if (ga.outHalf) {
                __half* hC = (__half*)ga.C + (size_t)zb * ga.sCz + (size_t)zh * ga.sCh;
                const int Cc = n0 + cl;
                const int p0i = (Cc & ~31) + tr4((Cc >> 1) & 15) * 2;
                *(__half2*)(hC + (size_t)row0 * ga.ldc + p0i) = __floats2half2_rn(v00, v01);
                *(__half2*)(hC + (size_t)(row0 + 8) * ga.ldc + p0i) = __floats2half2_rn(v10, v11);
            } else {
                float* fC = (float*)ga.C + (size_t)zb * ga.sCz + (size_t)zh * ga.sCh;
                *(float2*)(fC + (size_t)row0 * ga.ldc + n0 + cl) = make_float2(v00, v01);
                *(float2*)(fC + (size_t)(row0 + 8) * ga.ldc + n0 + cl) = make_float2(v10, v11);
            }
        }
    }
#undef ISSUE
}

// ===== fp32 -> fp16 with pair-tr4 permutation within 32-elem groups =====
// out chunk o4 (8 halves = 4 pairs) holds logical pairs {t, t+4, t+8, t+12},
// t = o4 & 3, of group (8*o4) & ~31.
__global__ __launch_bounds__(256) void half_perm(
    const float* __restrict__ in, __half* __restrict__ out, int n16)
{
    const int o4 = blockIdx.x * 256 + threadIdx.x;
    if (o4 < n16) {
        const int eg = (o4 * 8) & ~31;       // group base (elements)
        const int t = o4 & 3;
        uint4 o;
        float2 f0 = *(const float2*)(in + eg + (t + 0) * 2);
        float2 f1 = *(const float2*)(in + eg + (t + 4) * 2);
        float2 f2 = *(const float2*)(in + eg + (t + 8) * 2);
        float2 f3 = *(const float2*)(in + eg + (t + 12) * 2);
        o.x = h2u(__floats2half2_rn(f0.x, f0.y));
        o.y = h2u(__floats2half2_rn(f1.x, f1.y));
        o.z = h2u(__floats2half2_rn(f2.x, f2.y));
        o.w = h2u(__floats2half2_rn(f3.x, f3.y));
        ((uint4*)out)[o4] = o;
    }
}

// ===== W transpose + fp16 + k-permute: Wt[n][perm(k)] = h(W[k][n]) =====
__global__ __launch_bounds__(256) void transpose_w(
    const float* __restrict__ W0, const float* __restrict__ W1,
    const float* __restrict__ W2, __half* __restrict__ Wt)
{
    __shared__ float t[32][33];
    const float* W = (blockIdx.z == 0) ? W0 : (blockIdx.z == 1) ? W1 : W2;
    __half* O = Wt + (size_t)blockIdx.z * ND * DH;
    const int x0 = blockIdx.x * 32, y0 = blockIdx.y * 32;
    const int tx = threadIdx.x, ty = threadIdx.y;
#pragma unroll
    for (int i = 0; i < 32; i += 8)
        t[ty + i][tx] = W[(size_t)(y0 + ty + i) * ND + x0 + tx];
    __syncthreads();
    const int kp = y0 + tr4(tx >> 1) * 2 + (tx & 1);
#pragma unroll
    for (int i = 0; i < 32; i += 8)
        O[(size_t)(x0 + ty + i) * DH + kp] = __float2half_rn(t[tx][ty + i]);
}

// ==== causal softmax: fp32 scores in (plain), fp16 probs out (permuted) ====
__global__ __launch_bounds__(256) void softmax_rows(
    const float* __restrict__ S, __half* __restrict__ P)
{
    const int r = blockIdx.x, z = blockIdx.y;
    const float4* row = (const float4*)(S + ((size_t)z * T_ + r) * T_);
    __half2* prow = (__half2*)(P + ((size_t)z * T_ + r) * T_);
    const int L = r + 1;
    const int Q = ((r | 127) + 1) >> 2;     // float4 count (128-pad)
    const int tid = threadIdx.x;
    const int wid = tid >> 5, lane = tid & 31;
    __shared__ float red[8];

    float4 v[2];
    float m = -1e30f;
#pragma unroll
    for (int it = 0; it < 2; ++it) {
        const int q = tid + it * 256;
        if (q < Q) {
            v[it] = row[q];
            const int j0 = q * 4;
            if (j0     < L) m = fmaxf(m, v[it].x);
            if (j0 + 1 < L) m = fmaxf(m, v[it].y);
            if (j0 + 2 < L) m = fmaxf(m, v[it].z);
            if (j0 + 3 < L) m = fmaxf(m, v[it].w);
        }
    }
#pragma unroll
    for (int o = 16; o > 0; o >>= 1) m = fmaxf(m, __shfl_xor_sync(~0u, m, o));
    if (lane == 0) red[wid] = m;
    __syncthreads();
    m = fmaxf(fmaxf(fmaxf(red[0], red[1]), fmaxf(red[2], red[3])),
              fmaxf(fmaxf(red[4], red[5]), fmaxf(red[6], red[7])));
    __syncthreads();

    float sum = 0.f;
#pragma unroll
    for (int it = 0; it < 2; ++it) {
        const int q = tid + it * 256;
        if (q < Q) {
            const int j0 = q * 4;
            v[it].x = (j0     < L) ? __expf(v[it].x - m) : 0.f;
            v[it].y = (j0 + 1 < L) ? __expf(v[it].y - m) : 0.f;
            v[it].z = (j0 + 2 < L) ? __expf(v[it].z - m) : 0.f;
            v[it].w = (j0 + 3 < L) ? __expf(v[it].w - m) : 0.f;
            sum += v[it].x + v[it].y + v[it].z + v[it].w;
        }
    }
#pragma unroll
    for (int o = 16; o > 0; o >>= 1) sum += __shfl_xor_sync(~0u, sum, o);
    if (lane == 0) red[wid] = sum;
    __syncthreads();
    const float inv = 1.0f / (red[0] + red[1] + red[2] + red[3] +
                              red[4] + red[5] + red[6] + red[7]);

#pragma unroll
    for (int it = 0; it < 2; ++it) {
        const int q = tid + it * 256;
        if (q < Q) {
            const int P0 = 2 * q, P1 = 2 * q + 1;   // logical pair indices
            const int o0 = (P0 & ~15) + tr4(P0 & 15);
            const int o1 = (P1 & ~15) + tr4(P1 & 15);
            prow[o0] = __floats2half2_rn(v[it].x * inv, v[it].y * inv);
            prow[o1] = __floats2half2_rn(v[it].z * inv, v[it].w * inv);
        }
    }
}

// =====================================================================
extern "C" void kernel_launch(void* const* d_in, const int* in_sizes, int n_in,
                              void* d_out, int out_size)
{
    const float* query = (const float*)d_in[0];
    const float* value = (const float*)d_in[1];
    const float* Wq    = (const float*)d_in[2];
    const float* bq    = (const float*)d_in[3];
    const float* Wk    = (const float*)d_in[4];
    const float* bk    = (const float*)d_in[5];
    const float* Wv    = (const float*)d_in[6];
    const float* bv    = (const float*)d_in[7];
    float* out = (float*)d_out;

    __half *q, *k, *vt, *p, *wt, *qr, *vr;
    float *s;
    cudaGetSymbolAddress((void**)&q,  g_q);
    cudaGetSymbolAddress((void**)&k,  g_k);
    cudaGetSymbolAddress((void**)&vt, g_vt);
    cudaGetSymbolAddress((void**)&s,  g_s);
    cudaGetSymbolAddress((void**)&p,  g_p);
    cudaGetSymbolAddress((void**)&wt, g_wt);
    cudaGetSymbolAddress((void**)&qr, g_qr);
    cudaGetSymbolAddress((void**)&vr, g_vr);

    cudaFuncSetAttribute(gemm_tc, cudaFuncAttributeMaxDynamicSharedMemorySize, SMEM_BYTES);

    const int n16 = BT * DH / 8;
    half_perm<<<n16 / 256, 256>>>(query, qr, n16);
    half_perm<<<n16 / 256, 256>>>(value, vr, n16);
    transpose_w<<<dim3(ND / 32, DH / 32, 3), dim3(32, 8)>>>(Wq, Wk, Wv, wt);

    GemmArgs a;

    // 1. q = query @ Wq + bq   (fp16 permuted out)
    a = { qr, 0, 0, DH,
          wt + 0 * (size_t)ND * DH, 0, 0, DH,
          q, 0, 0, ND,
          DH, 1, bq, 1, 1.0f, 0, 1 };
    gemm_tc<<<dim3(ND / TN, BT / TM, 1), 256, SMEM_BYTES>>>(a);

    // 2. k = value @ Wk + bk   (fp16 permuted out)
    a = { vr, 0, 0, DH,
          wt + 1 * (size_t)ND * DH, 0, 0, DH,
          k, 0, 0, ND,
          DH, 1, bk, 1, 1.0f, 0, 1 };
    gemm_tc<<<dim3(ND / TN, BT / TM, 1), 256, SMEM_BYTES>>>(a);

    // 3. vt = Wv^T @ value^T + bv  (fp16, t-permuted out)
    a = { wt + 2 * (size_t)ND * DH, 0, 0, DH,
          vr, (long long)T_ * DH, 0, DH,
          vt, (long long)ND * T_, 0, T_,
          DH, 1, bv, 2, 1.0f, 0, 1 };
    gemm_tc<<<dim3(T_ / TN, ND / TM, B_), 256, SMEM_BYTES>>>(a);

    // 4. scores = scale * q @ k^T  (causal tile skip; fp32 plain out)
    a = { q, (long long)T_ * ND, DH, ND,
          k, (long long)T_ * ND, DH, ND,
          s, 8LL * T_ * T_, (long long)T_ * T_, T_,
          DH, H_, nullptr, 0, 0.044194173824159216f, 1, 0 };
    gemm_tc<<<dim3(T_ / TN, T_ / TM, B_ * H_), 256, SMEM_BYTES>>>(a);

    // 5. softmax: fp32 scores -> fp16 permuted probs (pad to 128)
    softmax_rows<<<dim3(T_, B_ * H_), 256>>>(s, p);

    // 6. out = P @ V   (K bounded at m0+128; fp32 plain out)
    a = { p, 8LL * T_ * T_, (long long)T_ * T_, T_,
          vt, (long long)ND * T_, (long long)DH * T_, T_,
          out, (long long)T_ * ND, DH, ND,
          T_, H_, nullptr, 0, 1.0f, 2, 0 };
    gemm_tc<<<dim3(DH / TN, T_ / TM, B_ * H_), 256, SMEM_BYTES>>>(a);
}